// round 3
// baseline (speedup 1.0000x reference)
#include <cuda_runtime.h>
#include <math.h>

#define T_STEPS 512
#define BATCH   64
#define DDIM    512
#define HDIM    512
#define G3      1536   // 3*HDIM

typedef unsigned long long u64;

// ---------------- packed f32x2 helpers (sm_100+: SASS FFMA2) ----------------
__device__ __forceinline__ u64 pack2(float x) {
    u64 r;
    asm("mov.b64 %0, {%1, %1};" : "=l"(r) : "r"(__float_as_uint(x)));
    return r;
}
__device__ __forceinline__ void fma2(u64& d, u64 a, u64 b) {
    asm("fma.rn.f32x2 %0, %1, %2, %0;" : "+l"(d) : "l"(a), "l"(b));
}
__device__ __forceinline__ float2 unpack2(u64 v) {
    float2 f;
    asm("mov.b64 {%0, %1}, %2;" : "=f"(f.x), "=f"(f.y) : "l"(v));
    return f;
}
__device__ __forceinline__ u64 d2u(double d) { return __double_as_longlong(d); }

// ---------------- static device scratch (no allocations allowed) ----------------
__device__ float g_gi[(size_t)T_STEPS * BATCH * G3];   // 192 MB: precomputed x@Wi + bi
__device__ float g_h[BATCH * HDIM];                    // recurrent hidden state buffer
__device__ int   g_bar[8];                             // per-batch-group barrier counters

// ---------------- barrier reset (graph-replay determinism) ----------------
__global__ void gru_reset_kernel() {
    if (threadIdx.x < 8) g_bar[threadIdx.x] = 0;
}

// ---------------- Phase 1: GI = X @ Wi + bi   (M=32768, K=512, N=1536) ----------------
__global__ __launch_bounds__(256) void gi_gemm_kernel(
    const float* __restrict__ X, const float* __restrict__ Wi, const float* __restrict__ bi)
{
    __shared__ float As[8][128];   // As[k][m]
    __shared__ float Bs[8][128];   // Bs[k][n]
    const int tid = threadIdx.x;
    const int bx  = blockIdx.x;    // N tile (12)
    const int by  = blockIdx.y;    // M tile (256)
    const int tx  = tid & 15;
    const int ty  = tid >> 4;

    // acc2[i][p]: row i, column pair p (cols 2p, 2p+1)
    u64 acc2[8][4];
    #pragma unroll
    for (int i = 0; i < 8; ++i)
        #pragma unroll
        for (int p = 0; p < 4; ++p) acc2[i][p] = 0ull;

    const int arow_l = tid >> 1;
    const int acol_l = (tid & 1) * 4;
    const int brow_l = tid >> 5;
    const int bcol_l = (tid & 31) * 4;
    const float* Aptr = X  + (size_t)(by * 128 + arow_l) * DDIM + acol_l;
    const float* Bptr = Wi + (size_t)brow_l * G3 + bx * 128 + bcol_l;

    for (int kk = 0; kk < DDIM; kk += 8) {
        float4 av = *(const float4*)(Aptr + kk);
        float4 bv = *(const float4*)(Bptr + (size_t)kk * G3);
        As[acol_l + 0][arow_l] = av.x;
        As[acol_l + 1][arow_l] = av.y;
        As[acol_l + 2][arow_l] = av.z;
        As[acol_l + 3][arow_l] = av.w;
        *(float4*)&Bs[brow_l][bcol_l] = bv;
        __syncthreads();
        #pragma unroll
        for (int k = 0; k < 8; ++k) {
            float4 a0 = *(const float4*)&As[k][ty * 8];
            float4 a1 = *(const float4*)&As[k][ty * 8 + 4];
            double2 bq0 = *(const double2*)&Bs[k][tx * 8];       // pairs (b0,b1),(b2,b3)
            double2 bq1 = *(const double2*)&Bs[k][tx * 8 + 4];   // pairs (b4,b5),(b6,b7)
            u64 bp[4] = {d2u(bq0.x), d2u(bq0.y), d2u(bq1.x), d2u(bq1.y)};
            u64 ap[8] = {pack2(a0.x), pack2(a0.y), pack2(a0.z), pack2(a0.w),
                         pack2(a1.x), pack2(a1.y), pack2(a1.z), pack2(a1.w)};
            #pragma unroll
            for (int i = 0; i < 8; ++i) {
                fma2(acc2[i][0], ap[i], bp[0]);
                fma2(acc2[i][1], ap[i], bp[1]);
                fma2(acc2[i][2], ap[i], bp[2]);
                fma2(acc2[i][3], ap[i], bp[3]);
            }
        }
        __syncthreads();
    }

    const int row0 = by * 128 + ty * 8;
    const int col0 = bx * 128 + tx * 8;
    float bvv[8];
    #pragma unroll
    for (int j = 0; j < 8; ++j) bvv[j] = bi[col0 + j];
    #pragma unroll
    for (int i = 0; i < 8; ++i) {
        float2 p0 = unpack2(acc2[i][0]);
        float2 p1 = unpack2(acc2[i][1]);
        float2 p2 = unpack2(acc2[i][2]);
        float2 p3 = unpack2(acc2[i][3]);
        float* orow = g_gi + (size_t)(row0 + i) * G3 + col0;
        float4 o0 = make_float4(p0.x + bvv[0], p0.y + bvv[1], p1.x + bvv[2], p1.y + bvv[3]);
        float4 o1 = make_float4(p2.x + bvv[4], p2.y + bvv[5], p3.x + bvv[6], p3.y + bvv[7]);
        *(float4*)(orow)     = o0;
        *(float4*)(orow + 4) = o1;
    }
}

// ---------------- Phase 2: persistent recurrence ----------------
// Grid: 128 CTAs = 8 batch-groups (8 batch rows each) x 16 column-CTAs (32 h-cols each).
// Each CTA keeps Wh slice [512][96] resident in SMEM for all 512 steps.

__device__ __forceinline__ int ld_acquire_gpu(const int* p) {
    int v;
    asm volatile("ld.acquire.gpu.s32 %0, [%1];" : "=r"(v) : "l"(p) : "memory");
    return v;
}

#define H_PAD 516                                    // padded row: banks {0,8,16,24} per b-group
#define REC_SMEM_FLOATS (512 * 96 + 8 * H_PAD + 4 * 32 * 24)
#define REC_SMEM_BYTES  (REC_SMEM_FLOATS * 4)        // 225,408 B

__global__ __launch_bounds__(128) void gru_rec_kernel(
    const float* __restrict__ h0, const float* __restrict__ Wh,
    const float* __restrict__ bhn, float* __restrict__ out)
{
    extern __shared__ float sm[];
    float* Whs   = sm;                   // [512][96]  (rows 384B -> 128B aligned)
    float* h_s   = sm + 512 * 96;        // [8][516]
    float* parts = h_s + 8 * H_PAD;      // [4 ksplit][32 og][24]

    const int tid  = threadIdx.x;
    const int bg   = blockIdx.x >> 4;    // batch group 0..7
    const int ic   = blockIdx.x & 15;    // col group 0..15
    const int lane = tid & 31;
    const int ks   = tid >> 5;           // warp index = k-split 0..3
    const int b0   = (lane >> 3) * 2;    // thread tile: 2 batch rows
    const int c0   = (lane & 7) * 4;     // thread tile: 4 cols per gate

    // --- one-time: load Wh slice into SMEM: Whs[k][g*32+cc] = Wh[k][g*512 + ic*32 + cc]
    for (int q = tid; q < 512 * 24; q += 128) {
        int k  = q / 24;
        int c4 = (q - k * 24) * 4;
        int g  = c4 >> 5;
        int cc = c4 & 31;
        float4 v = *(const float4*)&Wh[(size_t)k * G3 + g * 512 + ic * 32 + cc];
        *(float4*)&Whs[k * 96 + c4] = v;
    }

    // Output assignment: thread handles h_new (obA, occ0) and (obB, occ0)
    const int occ0 = tid & 31;           // column within the 32-col block
    const int obA  = tid >> 5;           // batch row 0..3
    const int obB  = obA + 4;            // batch row 4..7
    const int ci   = occ0 & 3;
    const int cgrp = occ0 >> 2;
    const int ogA  = (obA >> 1) * 8 + cgrp;
    const int ogB  = (obB >> 1) * 8 + cgrp;
    const int bb   = obA & 1;            // same for obB (+4 preserves bit 0)
    const int hcol = ic * 32 + occ0;     // global hidden column
    const float bh = bhn[hcol];

    __syncthreads();

    for (int t = 0; t < T_STEPS; ++t) {
        // --- load this batch group's h into SMEM (padded rows) ---
        const float* hsrc = (t == 0) ? (h0 + (size_t)bg * 8 * HDIM)
                                     : (g_h + (size_t)bg * 8 * HDIM);
        #pragma unroll 2
        for (int q = tid; q < 1024; q += 128) {
            int b  = q >> 7;
            int kq = (q & 127) * 4;
            float4 v = *(const float4*)&hsrc[b * HDIM + kq];
            *(float4*)&h_s[b * H_PAD + kq] = v;
        }
        // --- prefetch gi values (DRAM latency hidden behind the GEMM) ---
        const float* giA = g_gi + ((size_t)t * BATCH + bg * 8 + obA) * G3 + hcol;
        const float* giB = g_gi + ((size_t)t * BATCH + bg * 8 + obB) * G3 + hcol;
        float grA = giA[0], gzA = giA[512], gnA = giA[1024];
        float grB = giB[0], gzB = giB[512], gnB = giB[1024];
        __syncthreads();

        // --- register-tiled GEMM with packed f32x2 (FFMA2):
        //     acc pairs over adjacent columns; W pairs load pre-packed as double2.
        //     accA/accB layout: {r01, r23, z01, z23, n01, n23} for batch rows b0 / b0+1.
        u64 accA[6], accB[6];
        #pragma unroll
        for (int i = 0; i < 6; ++i) { accA[i] = 0ull; accB[i] = 0ull; }
        const float* hA = &h_s[b0 * H_PAD + ks * 128];
        const float* hB = &h_s[(b0 + 1) * H_PAD + ks * 128];
        const float* wp = &Whs[(ks * 128) * 96 + c0];
        #pragma unroll 8
        for (int i = 0; i < 128; ++i) {
            u64 A0 = pack2(hA[i]);
            u64 A1 = pack2(hB[i]);
            double2 wr = *(const double2*)(wp);        // r cols (c0,c0+1),(c0+2,c0+3)
            double2 wz = *(const double2*)(wp + 32);
            double2 wn = *(const double2*)(wp + 64);
            u64 wr0 = d2u(wr.x), wr1 = d2u(wr.y);
            u64 wz0 = d2u(wz.x), wz1 = d2u(wz.y);
            u64 wn0 = d2u(wn.x), wn1 = d2u(wn.y);
            fma2(accA[0], A0, wr0); fma2(accA[1], A0, wr1);
            fma2(accA[2], A0, wz0); fma2(accA[3], A0, wz1);
            fma2(accA[4], A0, wn0); fma2(accA[5], A0, wn1);
            fma2(accB[0], A1, wr0); fma2(accB[1], A1, wr1);
            fma2(accB[2], A1, wz0); fma2(accB[3], A1, wz1);
            fma2(accB[4], A1, wn0); fma2(accB[5], A1, wn1);
            wp += 96;
        }
        // --- stage k-split partials (same float layout as scalar version) ---
        u64* pp = (u64*)&parts[(ks * 32 + lane) * 24];
        *(ulonglong2*)(pp + 0)  = make_ulonglong2(accA[0], accA[1]);
        *(ulonglong2*)(pp + 2)  = make_ulonglong2(accA[2], accA[3]);
        *(ulonglong2*)(pp + 4)  = make_ulonglong2(accA[4], accA[5]);
        *(ulonglong2*)(pp + 6)  = make_ulonglong2(accB[0], accB[1]);
        *(ulonglong2*)(pp + 8)  = make_ulonglong2(accB[2], accB[3]);
        *(ulonglong2*)(pp + 10) = make_ulonglong2(accB[4], accB[5]);
        __syncthreads();

        // --- reduce k-splits + gates + write (2 h-outputs per thread) ---
        {
            const float* pA = &parts[ogA * 24 + bb * 12 + ci];
            float sr = 0.f, sz = 0.f, sn = 0.f;
            #pragma unroll
            for (int k2 = 0; k2 < 4; ++k2) {
                const float* q = pA + k2 * (32 * 24);
                sr += q[0]; sz += q[4]; sn += q[8];
            }
            float rr   = 1.f / (1.f + __expf(-(grA + sr)));
            float zz   = 1.f / (1.f + __expf(-(gzA + sz)));
            float nn   = tanhf(gnA + rr * (sn + bh));
            float hold = h_s[obA * H_PAD + hcol];
            float hnew = (1.f - zz) * nn + zz * hold;
            int brow = bg * 8 + obA;
            g_h[brow * HDIM + hcol] = hnew;
            out[((size_t)t * BATCH + brow) * HDIM + hcol] = hnew;
        }
        {
            const float* pB = &parts[ogB * 24 + bb * 12 + ci];
            float sr = 0.f, sz = 0.f, sn = 0.f;
            #pragma unroll
            for (int k2 = 0; k2 < 4; ++k2) {
                const float* q = pB + k2 * (32 * 24);
                sr += q[0]; sz += q[4]; sn += q[8];
            }
            float rr   = 1.f / (1.f + __expf(-(gzB * 0.f + grB + sr)));
            float zz   = 1.f / (1.f + __expf(-(gzB + sz)));
            float nn   = tanhf(gnB + rr * (sn + bh));
            float hold = h_s[obB * H_PAD + hcol];
            float hnew = (1.f - zz) * nn + zz * hold;
            int brow = bg * 8 + obB;
            g_h[brow * HDIM + hcol] = hnew;
            out[((size_t)t * BATCH + brow) * HDIM + hcol] = hnew;
        }

        // --- 16-CTA batch-group barrier (monotonic counter, release/acquire) ---
        __threadfence();
        __syncthreads();
        if (tid == 0) {
            atomicAdd(&g_bar[bg], 1);
            const int target = (t + 1) * 16;
            while (ld_acquire_gpu(&g_bar[bg]) < target) { }
        }
        __syncthreads();
    }
}

// ---------------- launch ----------------
extern "C" void kernel_launch(void* const* d_in, const int* in_sizes, int n_in,
                              void* d_out, int out_size)
{
    const float* x   = (const float*)d_in[0];   // [T,B,D]
    const float* h0  = (const float*)d_in[1];   // [B,H]
    const float* Wi  = (const float*)d_in[2];   // [D,3H]
    const float* Wh  = (const float*)d_in[3];   // [H,3H]
    const float* bi  = (const float*)d_in[4];   // [3H]
    const float* bhn = (const float*)d_in[5];   // [H]
    float* out = (float*)d_out;                 // [T,B,H]
    (void)in_sizes; (void)n_in; (void)out_size;

    cudaFuncSetAttribute(gru_rec_kernel,
                         cudaFuncAttributeMaxDynamicSharedMemorySize, REC_SMEM_BYTES);

    gru_reset_kernel<<<1, 32>>>();

    dim3 g1(G3 / 128, (T_STEPS * BATCH) / 128);   // (12, 256)
    gi_gemm_kernel<<<g1, 256>>>(x, Wi, bi);

    gru_rec_kernel<<<128, 128, REC_SMEM_BYTES>>>(h0, Wh, bhn, out);
}

// round 5
// speedup vs baseline: 1.2832x; 1.2832x over previous
#include <cuda_runtime.h>
#include <cuda_bf16.h>
#include <math.h>
#include <stdint.h>

#define T_STEPS 512
#define BATCH   64
#define DDIM    512
#define HDIM    512
#define G3      1536   // 3*HDIM
#define MROWS   (T_STEPS * BATCH)   // 32768
#define KCAT    1536                // 3*DDIM : [Xh | Xl | Xh]

// ---------------- static device scratch ----------------
__device__ float         g_gi[(size_t)MROWS * G3];         // 192 MB fp32 GI
__device__ float         g_h[BATCH * HDIM];
__device__ int           g_bar[8];
__device__ __nv_bfloat16 g_xc[(size_t)MROWS * KCAT];       // 96 MB  A' = [Xh|Xl|Xh]
__device__ __nv_bfloat16 g_bm[(size_t)G3 * KCAT];          // 4.5 MB B'[n][k]

// ---------------- helpers ----------------
__device__ __forceinline__ uint32_t s2u(const void* p) {
    return (uint32_t)__cvta_generic_to_shared(p);
}
__device__ __forceinline__ unsigned short f2bf(float x) {
    __nv_bfloat16 b = __float2bfloat16(x);
    return *reinterpret_cast<unsigned short*>(&b);
}
__device__ __forceinline__ float bf2f(unsigned short u) {
    __nv_bfloat16 b = *reinterpret_cast<__nv_bfloat16*>(&u);
    return __bfloat162float(b);
}
__device__ __forceinline__ void ldsm_x4(uint32_t& r0, uint32_t& r1, uint32_t& r2,
                                        uint32_t& r3, uint32_t addr) {
    asm volatile("ldmatrix.sync.aligned.m8n8.x4.shared.b16 {%0,%1,%2,%3}, [%4];"
                 : "=r"(r0), "=r"(r1), "=r"(r2), "=r"(r3) : "r"(addr));
}
__device__ __forceinline__ void mma16816(float* c, const uint32_t* a, uint32_t b0, uint32_t b1) {
    asm volatile(
        "mma.sync.aligned.m16n8k16.row.col.f32.bf16.bf16.f32 "
        "{%0,%1,%2,%3}, {%4,%5,%6,%7}, {%8,%9}, {%0,%1,%2,%3};"
        : "+f"(c[0]), "+f"(c[1]), "+f"(c[2]), "+f"(c[3])
        : "r"(a[0]), "r"(a[1]), "r"(a[2]), "r"(a[3]), "r"(b0), "r"(b1));
}

// ---------------- barrier reset ----------------
__global__ void gru_reset_kernel() {
    if (threadIdx.x < 8) g_bar[threadIdx.x] = 0;
}

// ---------------- bf16 hi/lo conversion of X -> g_xc ----------------
__global__ __launch_bounds__(256) void conv_x_kernel(const float* __restrict__ X) {
    size_t idx = ((size_t)blockIdx.x * 256 + threadIdx.x) * 4;   // over MROWS*DDIM
    size_t m = idx >> 9;
    size_t k = idx & 511;
    float4 v = *(const float4*)(X + idx);
    unsigned short h0 = f2bf(v.x), h1 = f2bf(v.y), h2 = f2bf(v.z), h3 = f2bf(v.w);
    unsigned short l0 = f2bf(v.x - bf2f(h0));
    unsigned short l1 = f2bf(v.y - bf2f(h1));
    unsigned short l2 = f2bf(v.z - bf2f(h2));
    unsigned short l3 = f2bf(v.w - bf2f(h3));
    ushort4 hv = make_ushort4(h0, h1, h2, h3);
    ushort4 lv = make_ushort4(l0, l1, l2, l3);
    ushort4* row = (ushort4*)(g_xc + m * KCAT);
    row[(k) >> 2]        = hv;   // segment 0: Xh
    row[(512 + k) >> 2]  = lv;   // segment 1: Xl
    row[(1024 + k) >> 2] = hv;   // segment 2: Xh
}

// ---------------- Wi -> B'[n][k] bf16 (transpose + hi/lo concat) ----------------
__global__ __launch_bounds__(256) void conv_w_kernel(const float* __restrict__ Wi) {
    __shared__ float tl[32][33];
    const int tx = threadIdx.x;        // 0..31
    const int ty = threadIdx.y;        // 0..7
    const int k0 = blockIdx.x * 32;    // 16 blocks
    const int n0 = blockIdx.y * 32;    // 48 blocks
    #pragma unroll
    for (int i = 0; i < 4; ++i) {
        int kk = ty + i * 8;
        tl[kk][tx] = Wi[(size_t)(k0 + kk) * G3 + n0 + tx];
    }
    __syncthreads();
    #pragma unroll
    for (int i = 0; i < 4; ++i) {
        int n = n0 + ty + i * 8;
        float v = tl[tx][ty + i * 8];          // = Wi[k0+tx][n]
        unsigned short hi = f2bf(v);
        unsigned short lo = f2bf(v - bf2f(hi));
        __nv_bfloat16* row = g_bm + (size_t)n * KCAT;
        *reinterpret_cast<unsigned short*>(row + k0 + tx)        = hi;  // seg0: Wh
        *reinterpret_cast<unsigned short*>(row + 512 + k0 + tx)  = hi;  // seg1: Wh (pairs Xl)
        *reinterpret_cast<unsigned short*>(row + 1024 + k0 + tx) = lo;  // seg2: Wl (pairs Xh)
    }
}

// ---------------- Phase 1: GI = A' @ B'^T via mma.sync bf16 ----------------
// Block tile 128x128, K-chunk 32, double-buffered SMEM, 8 warps (2 M x 4 N),
// warp tile 64x32 = 4x4 m16n8k16 tiles.
#define NKCH (KCAT / 32)    // 48

__global__ __launch_bounds__(256) void gi_mma_kernel(const float* __restrict__ bi) {
    __shared__ __align__(16) __nv_bfloat16 As[2][128][40];   // padded rows (80B)
    __shared__ __align__(16) __nv_bfloat16 Bs[2][128][40];

    const int tid  = threadIdx.x;
    const int lane = tid & 31;
    const int wid  = tid >> 5;
    const int wm   = wid & 1;        // 0..1 -> m offset wm*64
    const int wn   = wid >> 1;       // 0..3 -> n offset wn*32
    const int bx   = blockIdx.x;     // N tile (12)
    const int by   = blockIdx.y;     // M tile (256)

    // global load mapping: thread covers (row = tid>>1, two 16B chunks c0, c0+1)
    const int grow = tid >> 1;
    const int gc0  = (tid & 1) * 2;
    const __nv_bfloat16* Ag = g_xc + (size_t)(by * 128 + grow) * KCAT + gc0 * 8;
    const __nv_bfloat16* Bg = g_bm + (size_t)(bx * 128 + grow) * KCAT + gc0 * 8;

    float acc[4][4][4];
    #pragma unroll
    for (int mt = 0; mt < 4; ++mt)
        #pragma unroll
        for (int nt = 0; nt < 4; ++nt)
            #pragma unroll
            for (int i = 0; i < 4; ++i) acc[mt][nt][i] = 0.f;

    // preload chunk 0 into buf 0
    {
        uint4 a0 = *(const uint4*)(Ag);
        uint4 a1 = *(const uint4*)(Ag + 8);
        uint4 b0 = *(const uint4*)(Bg);
        uint4 b1 = *(const uint4*)(Bg + 8);
        *(uint4*)&As[0][grow][gc0 * 8]       = a0;
        *(uint4*)&As[0][grow][(gc0 + 1) * 8] = a1;
        *(uint4*)&Bs[0][grow][gc0 * 8]       = b0;
        *(uint4*)&Bs[0][grow][(gc0 + 1) * 8] = b1;
    }
    __syncthreads();

    // ldmatrix source addresses (depend only on lane)
    const int lrow = lane & 15;
    const int lkof = (lane >> 4) * 8;

    #pragma unroll 1
    for (int kt = 0; kt < NKCH; ++kt) {
        const int buf = kt & 1;
        uint4 pa0, pa1, pb0, pb1;
        if (kt + 1 < NKCH) {
            const __nv_bfloat16* An = Ag + (kt + 1) * 32;
            const __nv_bfloat16* Bn = Bg + (kt + 1) * 32;
            pa0 = *(const uint4*)(An);
            pa1 = *(const uint4*)(An + 8);
            pb0 = *(const uint4*)(Bn);
            pb1 = *(const uint4*)(Bn + 8);
        }

        #pragma unroll
        for (int ks = 0; ks < 2; ++ks) {
            uint32_t a[4][4];
            uint32_t bb[2][4];
            #pragma unroll
            for (int mt = 0; mt < 4; ++mt) {
                uint32_t ad = s2u(&As[buf][wm * 64 + mt * 16 + lrow][ks * 16 + lkof]);
                ldsm_x4(a[mt][0], a[mt][1], a[mt][2], a[mt][3], ad);
            }
            #pragma unroll
            for (int bt = 0; bt < 2; ++bt) {
                uint32_t bd = s2u(&Bs[buf][wn * 32 + bt * 16 + lrow][ks * 16 + lkof]);
                ldsm_x4(bb[bt][0], bb[bt][1], bb[bt][2], bb[bt][3], bd);
            }
            #pragma unroll
            for (int mt = 0; mt < 4; ++mt)
                #pragma unroll
                for (int nt = 0; nt < 4; ++nt) {
                    const int bt = nt >> 1, od = nt & 1;
                    mma16816(acc[mt][nt], a[mt], bb[bt][od], bb[bt][od + 2]);
                }
        }

        if (kt + 1 < NKCH) {
            const int nb = buf ^ 1;
            *(uint4*)&As[nb][grow][gc0 * 8]       = pa0;
            *(uint4*)&As[nb][grow][(gc0 + 1) * 8] = pa1;
            *(uint4*)&Bs[nb][grow][gc0 * 8]       = pb0;
            *(uint4*)&Bs[nb][grow][(gc0 + 1) * 8] = pb1;
            __syncthreads();
        }
    }

    // epilogue: D[m][n] + bi[n]
    #pragma unroll
    for (int mt = 0; mt < 4; ++mt) {
        const int row = by * 128 + wm * 64 + mt * 16 + (lane >> 2);
        #pragma unroll
        for (int nt = 0; nt < 4; ++nt) {
            const int col = bx * 128 + wn * 32 + nt * 8 + (lane & 3) * 2;
            const float b0 = bi[col], b1 = bi[col + 1];
            float* p0 = g_gi + (size_t)row * G3 + col;
            float* p1 = g_gi + (size_t)(row + 8) * G3 + col;
            *(float2*)p0 = make_float2(acc[mt][nt][0] + b0, acc[mt][nt][1] + b1);
            *(float2*)p1 = make_float2(acc[mt][nt][2] + b0, acc[mt][nt][3] + b1);
        }
    }
}

// ---------------- Phase 2: persistent recurrence (scalar fp32, proven) ----------------
__device__ __forceinline__ int ld_acquire_gpu(const int* p) {
    int v;
    asm volatile("ld.acquire.gpu.s32 %0, [%1];" : "=r"(v) : "l"(p) : "memory");
    return v;
}

#define H_PAD 516
#define REC_SMEM_FLOATS (512 * 96 + 8 * H_PAD + 4 * 32 * 24)
#define REC_SMEM_BYTES  (REC_SMEM_FLOATS * 4)

__global__ __launch_bounds__(128) void gru_rec_kernel(
    const float* __restrict__ h0, const float* __restrict__ Wh,
    const float* __restrict__ bhn, float* __restrict__ out)
{
    extern __shared__ float sm[];
    float* Whs   = sm;
    float* h_s   = sm + 512 * 96;
    float* parts = h_s + 8 * H_PAD;

    const int tid  = threadIdx.x;
    const int bg   = blockIdx.x >> 4;
    const int ic   = blockIdx.x & 15;
    const int lane = tid & 31;
    const int ks   = tid >> 5;
    const int b0   = (lane >> 3) * 2;
    const int c0   = (lane & 7) * 4;

    for (int q = tid; q < 512 * 24; q += 128) {
        int k  = q / 24;
        int c4 = (q - k * 24) * 4;
        int g  = c4 >> 5;
        int cc = c4 & 31;
        float4 v = *(const float4*)&Wh[(size_t)k * G3 + g * 512 + ic * 32 + cc];
        *(float4*)&Whs[k * 96 + c4] = v;
    }

    const int occ0 = tid & 31;
    const int obA  = tid >> 5;
    const int obB  = obA + 4;
    const int ci   = occ0 & 3;
    const int cgrp = occ0 >> 2;
    const int ogA  = (obA >> 1) * 8 + cgrp;
    const int ogB  = (obB >> 1) * 8 + cgrp;
    const int bb   = obA & 1;
    const int hcol = ic * 32 + occ0;
    const float bh = bhn[hcol];

    __syncthreads();

    for (int t = 0; t < T_STEPS; ++t) {
        const float* hsrc = (t == 0) ? (h0 + (size_t)bg * 8 * HDIM)
                                     : (g_h + (size_t)bg * 8 * HDIM);
        #pragma unroll 2
        for (int q = tid; q < 1024; q += 128) {
            int b  = q >> 7;
            int kq = (q & 127) * 4;
            float4 v = *(const float4*)&hsrc[b * HDIM + kq];
            *(float4*)&h_s[b * H_PAD + kq] = v;
        }
        const float* giA = g_gi + ((size_t)t * BATCH + bg * 8 + obA) * G3 + hcol;
        const float* giB = g_gi + ((size_t)t * BATCH + bg * 8 + obB) * G3 + hcol;
        float grA = giA[0], gzA = giA[512], gnA = giA[1024];
        float grB = giB[0], gzB = giB[512], gnB = giB[1024];
        __syncthreads();

        float acc[24];
        #pragma unroll
        for (int i = 0; i < 24; ++i) acc[i] = 0.f;
        const float* hA = &h_s[b0 * H_PAD + ks * 128];
        const float* hB = &h_s[(b0 + 1) * H_PAD + ks * 128];
        const float* wp = &Whs[(ks * 128) * 96 + c0];
        #pragma unroll 8
        for (int i = 0; i < 128; ++i) {
            float a0 = hA[i];
            float a1 = hB[i];
            float4 wr = *(const float4*)(wp);
            float4 wz = *(const float4*)(wp + 32);
            float4 wn = *(const float4*)(wp + 64);
            acc[0]  = fmaf(a0, wr.x, acc[0]);  acc[1]  = fmaf(a0, wr.y, acc[1]);
            acc[2]  = fmaf(a0, wr.z, acc[2]);  acc[3]  = fmaf(a0, wr.w, acc[3]);
            acc[4]  = fmaf(a0, wz.x, acc[4]);  acc[5]  = fmaf(a0, wz.y, acc[5]);
            acc[6]  = fmaf(a0, wz.z, acc[6]);  acc[7]  = fmaf(a0, wz.w, acc[7]);
            acc[8]  = fmaf(a0, wn.x, acc[8]);  acc[9]  = fmaf(a0, wn.y, acc[9]);
            acc[10] = fmaf(a0, wn.z, acc[10]); acc[11] = fmaf(a0, wn.w, acc[11]);
            acc[12] = fmaf(a1, wr.x, acc[12]); acc[13] = fmaf(a1, wr.y, acc[13]);
            acc[14] = fmaf(a1, wr.z, acc[14]); acc[15] = fmaf(a1, wr.w, acc[15]);
            acc[16] = fmaf(a1, wz.x, acc[16]); acc[17] = fmaf(a1, wz.y, acc[17]);
            acc[18] = fmaf(a1, wz.z, acc[18]); acc[19] = fmaf(a1, wz.w, acc[19]);
            acc[20] = fmaf(a1, wn.x, acc[20]); acc[21] = fmaf(a1, wn.y, acc[21]);
            acc[22] = fmaf(a1, wn.z, acc[22]); acc[23] = fmaf(a1, wn.w, acc[23]);
            wp += 96;
        }
        float* pp = &parts[(ks * 32 + lane) * 24];
        *(float4*)(pp + 0)  = make_float4(acc[0],  acc[1],  acc[2],  acc[3]);
        *(float4*)(pp + 4)  = make_float4(acc[4],  acc[5],  acc[6],  acc[7]);
        *(float4*)(pp + 8)  = make_float4(acc[8],  acc[9],  acc[10], acc[11]);
        *(float4*)(pp + 12) = make_float4(acc[12], acc[13], acc[14], acc[15]);
        *(float4*)(pp + 16) = make_float4(acc[16], acc[17], acc[18], acc[19]);
        *(float4*)(pp + 20) = make_float4(acc[20], acc[21], acc[22], acc[23]);
        __syncthreads();

        {
            const float* pA = &parts[ogA * 24 + bb * 12 + ci];
            float sr = 0.f, sz = 0.f, sn = 0.f;
            #pragma unroll
            for (int k2 = 0; k2 < 4; ++k2) {
                const float* q = pA + k2 * (32 * 24);
                sr += q[0]; sz += q[4]; sn += q[8];
            }
            float rr   = 1.f / (1.f + __expf(-(grA + sr)));
            float zz   = 1.f / (1.f + __expf(-(gzA + sz)));
            float nn   = tanhf(gnA + rr * (sn + bh));
            float hold = h_s[obA * H_PAD + hcol];
            float hnew = (1.f - zz) * nn + zz * hold;
            int brow = bg * 8 + obA;
            g_h[brow * HDIM + hcol] = hnew;
            out[((size_t)t * BATCH + brow) * HDIM + hcol] = hnew;
        }
        {
            const float* pB = &parts[ogB * 24 + bb * 12 + ci];
            float sr = 0.f, sz = 0.f, sn = 0.f;
            #pragma unroll
            for (int k2 = 0; k2 < 4; ++k2) {
                const float* q = pB + k2 * (32 * 24);
                sr += q[0]; sz += q[4]; sn += q[8];
            }
            float rr   = 1.f / (1.f + __expf(-(grB + sr)));
            float zz   = 1.f / (1.f + __expf(-(gzB + sz)));
            float nn   = tanhf(gnB + rr * (sn + bh));
            float hold = h_s[obB * H_PAD + hcol];
            float hnew = (1.f - zz) * nn + zz * hold;
            int brow = bg * 8 + obB;
            g_h[brow * HDIM + hcol] = hnew;
            out[((size_t)t * BATCH + brow) * HDIM + hcol] = hnew;
        }

        __threadfence();
        __syncthreads();
        if (tid == 0) {
            atomicAdd(&g_bar[bg], 1);
            const int target = (t + 1) * 16;
            while (ld_acquire_gpu(&g_bar[bg]) < target) { }
        }
        __syncthreads();
    }
}

// ---------------- launch ----------------
extern "C" void kernel_launch(void* const* d_in, const int* in_sizes, int n_in,
                              void* d_out, int out_size)
{
    const float* x   = (const float*)d_in[0];   // [T,B,D]
    const float* h0  = (const float*)d_in[1];   // [B,H]
    const float* Wi  = (const float*)d_in[2];   // [D,3H]
    const float* Wh  = (const float*)d_in[3];   // [H,3H]
    const float* bi  = (const float*)d_in[4];   // [3H]
    const float* bhn = (const float*)d_in[5];   // [H]
    float* out = (float*)d_out;                 // [T,B,H]
    (void)in_sizes; (void)n_in; (void)out_size;

    cudaFuncSetAttribute(gru_rec_kernel,
                         cudaFuncAttributeMaxDynamicSharedMemorySize, REC_SMEM_BYTES);

    gru_reset_kernel<<<1, 32>>>();

    conv_x_kernel<<<(MROWS * DDIM / 4) / 256, 256>>>(x);
    conv_w_kernel<<<dim3(16, 48), dim3(32, 8)>>>(Wi);

    dim3 g1(G3 / 128, MROWS / 128);   // (12, 256)
    gi_mma_kernel<<<g1, 256>>>(bi);

    gru_rec_kernel<<<128, 128, REC_SMEM_BYTES>>>(h0, Wh, bhn, out);
}

// round 6
// speedup vs baseline: 1.8356x; 1.4305x over previous
#include <cuda_runtime.h>
#include <cuda_bf16.h>
#include <math.h>
#include <stdint.h>

#define T_STEPS 512
#define BATCH   64
#define DDIM    512
#define HDIM    512
#define G3      1536   // 3*HDIM
#define MROWS   (T_STEPS * BATCH)   // 32768
#define KCAT    1536                // 3*DDIM : [Xh | Xl | Xh]

// ---------------- static device scratch ----------------
__device__ float         g_gi[(size_t)MROWS * G3];         // 192 MB fp32 GI
__device__ float         g_h[BATCH * HDIM];
__device__ int           g_bar[8];
__device__ __nv_bfloat16 g_xc[(size_t)MROWS * KCAT];       // 96 MB  A' = [Xh|Xl|Xh]
__device__ __nv_bfloat16 g_bm[(size_t)G3 * KCAT];          // 4.5 MB B'[n][k]

// ---------------- helpers ----------------
__device__ __forceinline__ uint32_t s2u(const void* p) {
    return (uint32_t)__cvta_generic_to_shared(p);
}
__device__ __forceinline__ unsigned short f2bf(float x) {
    __nv_bfloat16 b = __float2bfloat16(x);
    return *reinterpret_cast<unsigned short*>(&b);
}
__device__ __forceinline__ float bf2f(unsigned short u) {
    __nv_bfloat16 b = *reinterpret_cast<__nv_bfloat16*>(&u);
    return __bfloat162float(b);
}
__device__ __forceinline__ void ldsm_x4(uint32_t& r0, uint32_t& r1, uint32_t& r2,
                                        uint32_t& r3, uint32_t addr) {
    asm volatile("ldmatrix.sync.aligned.m8n8.x4.shared.b16 {%0,%1,%2,%3}, [%4];"
                 : "=r"(r0), "=r"(r1), "=r"(r2), "=r"(r3) : "r"(addr));
}
__device__ __forceinline__ void mma16816(float* c, const uint32_t* a, uint32_t b0, uint32_t b1) {
    asm volatile(
        "mma.sync.aligned.m16n8k16.row.col.f32.bf16.bf16.f32 "
        "{%0,%1,%2,%3}, {%4,%5,%6,%7}, {%8,%9}, {%0,%1,%2,%3};"
        : "+f"(c[0]), "+f"(c[1]), "+f"(c[2]), "+f"(c[3])
        : "r"(a[0]), "r"(a[1]), "r"(a[2]), "r"(a[3]), "r"(b0), "r"(b1));
}
__device__ __forceinline__ int ld_acquire_gpu(const int* p) {
    int v;
    asm volatile("ld.acquire.gpu.s32 %0, [%1];" : "=r"(v) : "l"(p) : "memory");
    return v;
}

// ---------------- barrier reset ----------------
__global__ void gru_reset_kernel() {
    if (threadIdx.x < 8) g_bar[threadIdx.x] = 0;
}

// ---------------- bf16 hi/lo conversion of X -> g_xc ----------------
__global__ __launch_bounds__(256) void conv_x_kernel(const float* __restrict__ X) {
    size_t idx = ((size_t)blockIdx.x * 256 + threadIdx.x) * 4;
    size_t m = idx >> 9;
    size_t k = idx & 511;
    float4 v = *(const float4*)(X + idx);
    unsigned short h0 = f2bf(v.x), h1 = f2bf(v.y), h2 = f2bf(v.z), h3 = f2bf(v.w);
    unsigned short l0 = f2bf(v.x - bf2f(h0));
    unsigned short l1 = f2bf(v.y - bf2f(h1));
    unsigned short l2 = f2bf(v.z - bf2f(h2));
    unsigned short l3 = f2bf(v.w - bf2f(h3));
    ushort4 hv = make_ushort4(h0, h1, h2, h3);
    ushort4 lv = make_ushort4(l0, l1, l2, l3);
    ushort4* row = (ushort4*)(g_xc + m * KCAT);
    row[(k) >> 2]        = hv;
    row[(512 + k) >> 2]  = lv;
    row[(1024 + k) >> 2] = hv;
}

// ---------------- Wi -> B'[n][k] bf16 (transpose + hi/lo concat) ----------------
__global__ __launch_bounds__(256) void conv_w_kernel(const float* __restrict__ Wi) {
    __shared__ float tl[32][33];
    const int tx = threadIdx.x;
    const int ty = threadIdx.y;
    const int k0 = blockIdx.x * 32;
    const int n0 = blockIdx.y * 32;
    #pragma unroll
    for (int i = 0; i < 4; ++i) {
        int kk = ty + i * 8;
        tl[kk][tx] = Wi[(size_t)(k0 + kk) * G3 + n0 + tx];
    }
    __syncthreads();
    #pragma unroll
    for (int i = 0; i < 4; ++i) {
        int n = n0 + ty + i * 8;
        float v = tl[tx][ty + i * 8];
        unsigned short hi = f2bf(v);
        unsigned short lo = f2bf(v - bf2f(hi));
        __nv_bfloat16* row = g_bm + (size_t)n * KCAT;
        *reinterpret_cast<unsigned short*>(row + k0 + tx)        = hi;
        *reinterpret_cast<unsigned short*>(row + 512 + k0 + tx)  = hi;
        *reinterpret_cast<unsigned short*>(row + 1024 + k0 + tx) = lo;
    }
}

// ---------------- Phase 1: GI = A' @ B'^T via mma.sync bf16 (unchanged) ----------------
#define NKCH (KCAT / 32)    // 48

__global__ __launch_bounds__(256) void gi_mma_kernel(const float* __restrict__ bi) {
    __shared__ __align__(16) __nv_bfloat16 As[2][128][40];
    __shared__ __align__(16) __nv_bfloat16 Bs[2][128][40];

    const int tid  = threadIdx.x;
    const int lane = tid & 31;
    const int wid  = tid >> 5;
    const int wm   = wid & 1;
    const int wn   = wid >> 1;
    const int bx   = blockIdx.x;
    const int by   = blockIdx.y;

    const int grow = tid >> 1;
    const int gc0  = (tid & 1) * 2;
    const __nv_bfloat16* Ag = g_xc + (size_t)(by * 128 + grow) * KCAT + gc0 * 8;
    const __nv_bfloat16* Bg = g_bm + (size_t)(bx * 128 + grow) * KCAT + gc0 * 8;

    float acc[4][4][4];
    #pragma unroll
    for (int mt = 0; mt < 4; ++mt)
        #pragma unroll
        for (int nt = 0; nt < 4; ++nt)
            #pragma unroll
            for (int i = 0; i < 4; ++i) acc[mt][nt][i] = 0.f;

    {
        uint4 a0 = *(const uint4*)(Ag);
        uint4 a1 = *(const uint4*)(Ag + 8);
        uint4 b0 = *(const uint4*)(Bg);
        uint4 b1 = *(const uint4*)(Bg + 8);
        *(uint4*)&As[0][grow][gc0 * 8]       = a0;
        *(uint4*)&As[0][grow][(gc0 + 1) * 8] = a1;
        *(uint4*)&Bs[0][grow][gc0 * 8]       = b0;
        *(uint4*)&Bs[0][grow][(gc0 + 1) * 8] = b1;
    }
    __syncthreads();

    const int lrow = lane & 15;
    const int lkof = (lane >> 4) * 8;

    #pragma unroll 1
    for (int kt = 0; kt < NKCH; ++kt) {
        const int buf = kt & 1;
        uint4 pa0, pa1, pb0, pb1;
        if (kt + 1 < NKCH) {
            const __nv_bfloat16* An = Ag + (kt + 1) * 32;
            const __nv_bfloat16* Bn = Bg + (kt + 1) * 32;
            pa0 = *(const uint4*)(An);
            pa1 = *(const uint4*)(An + 8);
            pb0 = *(const uint4*)(Bn);
            pb1 = *(const uint4*)(Bn + 8);
        }

        #pragma unroll
        for (int ks = 0; ks < 2; ++ks) {
            uint32_t a[4][4];
            uint32_t bb[2][4];
            #pragma unroll
            for (int mt = 0; mt < 4; ++mt) {
                uint32_t ad = s2u(&As[buf][wm * 64 + mt * 16 + lrow][ks * 16 + lkof]);
                ldsm_x4(a[mt][0], a[mt][1], a[mt][2], a[mt][3], ad);
            }
            #pragma unroll
            for (int bt = 0; bt < 2; ++bt) {
                uint32_t bd = s2u(&Bs[buf][wn * 32 + bt * 16 + lrow][ks * 16 + lkof]);
                ldsm_x4(bb[bt][0], bb[bt][1], bb[bt][2], bb[bt][3], bd);
            }
            #pragma unroll
            for (int mt = 0; mt < 4; ++mt)
                #pragma unroll
                for (int nt = 0; nt < 4; ++nt) {
                    const int bt = nt >> 1, od = nt & 1;
                    mma16816(acc[mt][nt], a[mt], bb[bt][od], bb[bt][od + 2]);
                }
        }

        if (kt + 1 < NKCH) {
            const int nb = buf ^ 1;
            *(uint4*)&As[nb][grow][gc0 * 8]       = pa0;
            *(uint4*)&As[nb][grow][(gc0 + 1) * 8] = pa1;
            *(uint4*)&Bs[nb][grow][gc0 * 8]       = pb0;
            *(uint4*)&Bs[nb][grow][(gc0 + 1) * 8] = pb1;
            __syncthreads();
        }
    }

    #pragma unroll
    for (int mt = 0; mt < 4; ++mt) {
        const int row = by * 128 + wm * 64 + mt * 16 + (lane >> 2);
        #pragma unroll
        for (int nt = 0; nt < 4; ++nt) {
            const int col = bx * 128 + wn * 32 + nt * 8 + (lane & 3) * 2;
            const float b0 = bi[col], b1 = bi[col + 1];
            float* p0 = g_gi + (size_t)row * G3 + col;
            float* p1 = g_gi + (size_t)(row + 8) * G3 + col;
            *(float2*)p0 = make_float2(acc[mt][nt][0] + b0, acc[mt][nt][1] + b1);
            *(float2*)p1 = make_float2(acc[mt][nt][2] + b0, acc[mt][nt][3] + b1);
        }
    }
}

// ---------------- Phase 2: persistent recurrence via mma.sync bf16 hi/lo ----------------
// 128 CTAs = 4 batch-groups (16 rows) x 32 col-CTAs (16 h-cols = 48 gate-cols).
// SMEM: Whi/Wlo [48][520] bf16 (resident), A hi/lo [16][520] bf16 (per step),
// parts [8][16][50] fp32 (k-split partials). Row stride 520 -> ldmatrix conflict-free.
#define BSTR 520
#define REC_SMEM_BYTES (2 * 48 * BSTR * 2 + 2 * 16 * BSTR * 2 + 8 * 16 * 50 * 4)  // 158720

__global__ __launch_bounds__(256) void gru_rec_kernel(
    const float* __restrict__ h0, const float* __restrict__ Wh,
    const float* __restrict__ bhn, float* __restrict__ out)
{
    extern __shared__ char smem[];
    __nv_bfloat16* Bh = (__nv_bfloat16*)smem;            // [48][520]
    __nv_bfloat16* Bl = Bh + 48 * BSTR;                  // [48][520]
    __nv_bfloat16* Ah = Bl + 48 * BSTR;                  // [16][520]
    __nv_bfloat16* Al = Ah + 16 * BSTR;                  // [16][520]
    float*        parts = (float*)(Al + 16 * BSTR);      // [8][16][50]

    const int tid  = threadIdx.x;
    const int lane = tid & 31;
    const int ks   = tid >> 5;         // warp = k-split 0..7 (64 k per pass)
    const int bg   = blockIdx.x >> 5;  // batch group 0..3 (16 rows)
    const int ic   = blockIdx.x & 31;  // col group 0..31  (16 h-cols)

    // --- one-time: Wh slice -> bf16 hi/lo in B layout [j][k], j: 0-15 r, 16-31 z, 32-47 n
    for (int q = tid; q < 48 * 512; q += 256) {
        int k = q / 48;
        int j = q - k * 48;
        int gc = (j >> 4) * 512 + ic * 16 + (j & 15);
        float v = Wh[(size_t)k * G3 + gc];
        unsigned short hi = f2bf(v);
        unsigned short lo = f2bf(v - bf2f(hi));
        *reinterpret_cast<unsigned short*>(Bh + j * BSTR + k) = hi;
        *reinterpret_cast<unsigned short*>(Bl + j * BSTR + k) = lo;
    }

    // gate-thread output assignment: 256 outputs = 16 rows x 16 cols
    const int orow = tid >> 4;
    const int oc   = tid & 15;
    const int hcol = ic * 16 + oc;
    const int brow = bg * 16 + orow;
    const float bh = bhn[hcol];

    const int lrow = lane & 15;
    const int lkof = (lane >> 4) * 8;

    __syncthreads();

    for (int t = 0; t < T_STEPS; ++t) {
        const float* hsrc = (t == 0) ? (h0 + (size_t)bg * 16 * HDIM)
                                     : (g_h + (size_t)bg * 16 * HDIM);

        // --- prefetch gi + h_old (LDG latency hidden behind conversion + GEMM) ---
        const float* gp = g_gi + ((size_t)t * BATCH + brow) * G3 + hcol;
        float gr = gp[0], gz = gp[512], gn = gp[1024];
        float hold = hsrc[orow * HDIM + hcol];

        // --- convert h group to bf16 hi/lo into A tiles ---
        #pragma unroll
        for (int q = tid; q < 2048; q += 256) {
            int m  = q >> 7;
            int kq = (q & 127) * 4;
            float4 v = *(const float4*)&hsrc[m * HDIM + kq];
            unsigned short h0b = f2bf(v.x), h1b = f2bf(v.y), h2b = f2bf(v.z), h3b = f2bf(v.w);
            unsigned short l0b = f2bf(v.x - bf2f(h0b));
            unsigned short l1b = f2bf(v.y - bf2f(h1b));
            unsigned short l2b = f2bf(v.z - bf2f(h2b));
            unsigned short l3b = f2bf(v.w - bf2f(h3b));
            *(ushort4*)(Ah + m * BSTR + kq) = make_ushort4(h0b, h1b, h2b, h3b);
            *(ushort4*)(Al + m * BSTR + kq) = make_ushort4(l0b, l1b, l2b, l3b);
        }
        __syncthreads();

        // --- 3-pass GEMM: (Ah,Bh) + (Al,Bh) + (Ah,Bl), warp k-slice = 64 ---
        float acc[6][4];
        #pragma unroll
        for (int nt = 0; nt < 6; ++nt)
            #pragma unroll
            for (int i = 0; i < 4; ++i) acc[nt][i] = 0.f;

        #pragma unroll
        for (int p = 0; p < 3; ++p) {
            const __nv_bfloat16* Asrc = (p == 1) ? Al : Ah;
            const __nv_bfloat16* Bsrc = (p == 2) ? Bl : Bh;
            #pragma unroll
            for (int ki = 0; ki < 4; ++ki) {
                const int k0 = ks * 64 + ki * 16;
                uint32_t a[4];
                ldsm_x4(a[0], a[1], a[2], a[3],
                        s2u(Asrc + lrow * BSTR + k0 + lkof));
                uint32_t bb[3][4];
                #pragma unroll
                for (int bt = 0; bt < 3; ++bt)
                    ldsm_x4(bb[bt][0], bb[bt][1], bb[bt][2], bb[bt][3],
                            s2u(Bsrc + (bt * 16 + lrow) * BSTR + k0 + lkof));
                #pragma unroll
                for (int nt = 0; nt < 6; ++nt) {
                    const int bt = nt >> 1, od = nt & 1;
                    mma16816(acc[nt], a, bb[bt][od], bb[bt][od + 2]);
                }
            }
        }

        // --- stage k-split partials ---
        {
            const int pr  = lane >> 2;
            const int pcb = (lane & 3) * 2;
            #pragma unroll
            for (int nt = 0; nt < 6; ++nt) {
                const int col = nt * 8 + pcb;
                *(float2*)&parts[(ks * 16 + pr) * 50 + col]     = make_float2(acc[nt][0], acc[nt][1]);
                *(float2*)&parts[(ks * 16 + pr + 8) * 50 + col] = make_float2(acc[nt][2], acc[nt][3]);
            }
        }
        __syncthreads();

        // --- reduce 8 k-splits + gates + write ---
        {
            float sr = 0.f, sz = 0.f, sn = 0.f;
            #pragma unroll
            for (int k2 = 0; k2 < 8; ++k2) {
                const float* q = &parts[(k2 * 16 + orow) * 50];
                sr += q[oc]; sz += q[16 + oc]; sn += q[32 + oc];
            }
            float rr   = 1.f / (1.f + __expf(-(gr + sr)));
            float zz   = 1.f / (1.f + __expf(-(gz + sz)));
            float nn   = tanhf(gn + rr * (sn + bh));
            float hnew = (1.f - zz) * nn + zz * hold;
            g_h[brow * HDIM + hcol] = hnew;
            out[((size_t)t * BATCH + brow) * HDIM + hcol] = hnew;
        }

        // --- 32-CTA batch-group barrier ---
        __threadfence();
        __syncthreads();
        if (tid == 0) {
            atomicAdd(&g_bar[bg], 1);
            const int target = (t + 1) * 32;
            while (ld_acquire_gpu(&g_bar[bg]) < target) { }
        }
        __syncthreads();
    }
}

// ---------------- launch ----------------
extern "C" void kernel_launch(void* const* d_in, const int* in_sizes, int n_in,
                              void* d_out, int out_size)
{
    const float* x   = (const float*)d_in[0];   // [T,B,D]
    const float* h0  = (const float*)d_in[1];   // [B,H]
    const float* Wi  = (const float*)d_in[2];   // [D,3H]
    const float* Wh  = (const float*)d_in[3];   // [H,3H]
    const float* bi  = (const float*)d_in[4];   // [3H]
    const float* bhn = (const float*)d_in[5];   // [H]
    float* out = (float*)d_out;                 // [T,B,H]
    (void)in_sizes; (void)n_in; (void)out_size;

    cudaFuncSetAttribute(gru_rec_kernel,
                         cudaFuncAttributeMaxDynamicSharedMemorySize, REC_SMEM_BYTES);

    gru_reset_kernel<<<1, 32>>>();

    conv_x_kernel<<<(MROWS * DDIM / 4) / 256, 256>>>(x);
    conv_w_kernel<<<dim3(16, 48), dim3(32, 8)>>>(Wi);

    dim3 g1(G3 / 128, MROWS / 128);   // (12, 256)
    gi_mma_kernel<<<g1, 256>>>(bi);

    gru_rec_kernel<<<128, 256, REC_SMEM_BYTES>>>(h0, Wh, bhn, out);
}

// round 7
// speedup vs baseline: 1.9017x; 1.0360x over previous
#include <cuda_runtime.h>
#include <cuda_bf16.h>
#include <math.h>
#include <stdint.h>

#define T_STEPS 512
#define BATCH   64
#define DDIM    512
#define HDIM    512
#define G3      1536   // 3*HDIM
#define MROWS   (T_STEPS * BATCH)   // 32768
#define KCAT    1536                // 3*DDIM : [Xh | Xl | Xh]

// ---------------- static device scratch ----------------
__device__ float         g_gi[(size_t)MROWS * G3];         // 192 MB fp32 GI
__device__ uint32_t      g_hp[BATCH * HDIM];               // packed bf16 hi/lo hidden state
__device__ int           g_bar[8];
__device__ __nv_bfloat16 g_xc[(size_t)MROWS * KCAT];       // 96 MB  A' = [Xh|Xl|Xh]
__device__ __nv_bfloat16 g_bm[(size_t)G3 * KCAT];          // 4.5 MB B'[n][k]

// ---------------- helpers ----------------
__device__ __forceinline__ uint32_t s2u(const void* p) {
    return (uint32_t)__cvta_generic_to_shared(p);
}
__device__ __forceinline__ unsigned short f2bf(float x) {
    __nv_bfloat16 b = __float2bfloat16(x);
    return *reinterpret_cast<unsigned short*>(&b);
}
__device__ __forceinline__ float bf2f(unsigned short u) {
    __nv_bfloat16 b = *reinterpret_cast<__nv_bfloat16*>(&u);
    return __bfloat162float(b);
}
__device__ __forceinline__ void ldsm_x4(uint32_t& r0, uint32_t& r1, uint32_t& r2,
                                        uint32_t& r3, uint32_t addr) {
    asm volatile("ldmatrix.sync.aligned.m8n8.x4.shared.b16 {%0,%1,%2,%3}, [%4];"
                 : "=r"(r0), "=r"(r1), "=r"(r2), "=r"(r3) : "r"(addr));
}
__device__ __forceinline__ void mma16816(float* c, const uint32_t* a, uint32_t b0, uint32_t b1) {
    asm volatile(
        "mma.sync.aligned.m16n8k16.row.col.f32.bf16.bf16.f32 "
        "{%0,%1,%2,%3}, {%4,%5,%6,%7}, {%8,%9}, {%0,%1,%2,%3};"
        : "+f"(c[0]), "+f"(c[1]), "+f"(c[2]), "+f"(c[3])
        : "r"(a[0]), "r"(a[1]), "r"(a[2]), "r"(a[3]), "r"(b0), "r"(b1));
}
__device__ __forceinline__ int ld_acquire_gpu(const int* p) {
    int v;
    asm volatile("ld.acquire.gpu.s32 %0, [%1];" : "=r"(v) : "l"(p) : "memory");
    return v;
}

// ---------------- init: barrier reset + pack h0 into g_hp ----------------
__global__ __launch_bounds__(1024) void gru_init_kernel(const float* __restrict__ h0) {
    const int idx = blockIdx.x * 1024 + threadIdx.x;   // grid 32 -> 32768
    if (blockIdx.x == 0 && threadIdx.x < 8) g_bar[threadIdx.x] = 0;
    float v = h0[idx];
    unsigned short hi = f2bf(v);
    unsigned short lo = f2bf(v - bf2f(hi));
    g_hp[idx] = ((uint32_t)hi << 16) | lo;
}

// ---------------- bf16 hi/lo conversion of X -> g_xc ----------------
__global__ __launch_bounds__(256) void conv_x_kernel(const float* __restrict__ X) {
    size_t idx = ((size_t)blockIdx.x * 256 + threadIdx.x) * 4;
    size_t m = idx >> 9;
    size_t k = idx & 511;
    float4 v = *(const float4*)(X + idx);
    unsigned short h0 = f2bf(v.x), h1 = f2bf(v.y), h2 = f2bf(v.z), h3 = f2bf(v.w);
    unsigned short l0 = f2bf(v.x - bf2f(h0));
    unsigned short l1 = f2bf(v.y - bf2f(h1));
    unsigned short l2 = f2bf(v.z - bf2f(h2));
    unsigned short l3 = f2bf(v.w - bf2f(h3));
    ushort4 hv = make_ushort4(h0, h1, h2, h3);
    ushort4 lv = make_ushort4(l0, l1, l2, l3);
    ushort4* row = (ushort4*)(g_xc + m * KCAT);
    row[(k) >> 2]        = hv;
    row[(512 + k) >> 2]  = lv;
    row[(1024 + k) >> 2] = hv;
}

// ---------------- Wi -> B'[n][k] bf16 (transpose + hi/lo concat) ----------------
__global__ __launch_bounds__(256) void conv_w_kernel(const float* __restrict__ Wi) {
    __shared__ float tl[32][33];
    const int tx = threadIdx.x;
    const int ty = threadIdx.y;
    const int k0 = blockIdx.x * 32;
    const int n0 = blockIdx.y * 32;
    #pragma unroll
    for (int i = 0; i < 4; ++i) {
        int kk = ty + i * 8;
        tl[kk][tx] = Wi[(size_t)(k0 + kk) * G3 + n0 + tx];
    }
    __syncthreads();
    #pragma unroll
    for (int i = 0; i < 4; ++i) {
        int n = n0 + ty + i * 8;
        float v = tl[tx][ty + i * 8];
        unsigned short hi = f2bf(v);
        unsigned short lo = f2bf(v - bf2f(hi));
        __nv_bfloat16* row = g_bm + (size_t)n * KCAT;
        *reinterpret_cast<unsigned short*>(row + k0 + tx)        = hi;
        *reinterpret_cast<unsigned short*>(row + 512 + k0 + tx)  = hi;
        *reinterpret_cast<unsigned short*>(row + 1024 + k0 + tx) = lo;
    }
}

// ---------------- Phase 1: GI = A' @ B'^T via mma.sync bf16 (unchanged, proven) ----------------
#define NKCH (KCAT / 32)    // 48

__global__ __launch_bounds__(256) void gi_mma_kernel(const float* __restrict__ bi) {
    __shared__ __align__(16) __nv_bfloat16 As[2][128][40];
    __shared__ __align__(16) __nv_bfloat16 Bs[2][128][40];

    const int tid  = threadIdx.x;
    const int lane = tid & 31;
    const int wid  = tid >> 5;
    const int wm   = wid & 1;
    const int wn   = wid >> 1;
    const int bx   = blockIdx.x;
    const int by   = blockIdx.y;

    const int grow = tid >> 1;
    const int gc0  = (tid & 1) * 2;
    const __nv_bfloat16* Ag = g_xc + (size_t)(by * 128 + grow) * KCAT + gc0 * 8;
    const __nv_bfloat16* Bg = g_bm + (size_t)(bx * 128 + grow) * KCAT + gc0 * 8;

    float acc[4][4][4];
    #pragma unroll
    for (int mt = 0; mt < 4; ++mt)
        #pragma unroll
        for (int nt = 0; nt < 4; ++nt)
            #pragma unroll
            for (int i = 0; i < 4; ++i) acc[mt][nt][i] = 0.f;

    {
        uint4 a0 = *(const uint4*)(Ag);
        uint4 a1 = *(const uint4*)(Ag + 8);
        uint4 b0 = *(const uint4*)(Bg);
        uint4 b1 = *(const uint4*)(Bg + 8);
        *(uint4*)&As[0][grow][gc0 * 8]       = a0;
        *(uint4*)&As[0][grow][(gc0 + 1) * 8] = a1;
        *(uint4*)&Bs[0][grow][gc0 * 8]       = b0;
        *(uint4*)&Bs[0][grow][(gc0 + 1) * 8] = b1;
    }
    __syncthreads();

    const int lrow = lane & 15;
    const int lkof = (lane >> 4) * 8;

    #pragma unroll 1
    for (int kt = 0; kt < NKCH; ++kt) {
        const int buf = kt & 1;
        uint4 pa0, pa1, pb0, pb1;
        if (kt + 1 < NKCH) {
            const __nv_bfloat16* An = Ag + (kt + 1) * 32;
            const __nv_bfloat16* Bn = Bg + (kt + 1) * 32;
            pa0 = *(const uint4*)(An);
            pa1 = *(const uint4*)(An + 8);
            pb0 = *(const uint4*)(Bn);
            pb1 = *(const uint4*)(Bn + 8);
        }

        #pragma unroll
        for (int ks = 0; ks < 2; ++ks) {
            uint32_t a[4][4];
            uint32_t bb[2][4];
            #pragma unroll
            for (int mt = 0; mt < 4; ++mt) {
                uint32_t ad = s2u(&As[buf][wm * 64 + mt * 16 + lrow][ks * 16 + lkof]);
                ldsm_x4(a[mt][0], a[mt][1], a[mt][2], a[mt][3], ad);
            }
            #pragma unroll
            for (int bt = 0; bt < 2; ++bt) {
                uint32_t bd = s2u(&Bs[buf][wn * 32 + bt * 16 + lrow][ks * 16 + lkof]);
                ldsm_x4(bb[bt][0], bb[bt][1], bb[bt][2], bb[bt][3], bd);
            }
            #pragma unroll
            for (int mt = 0; mt < 4; ++mt)
                #pragma unroll
                for (int nt = 0; nt < 4; ++nt) {
                    const int bt = nt >> 1, od = nt & 1;
                    mma16816(acc[mt][nt], a[mt], bb[bt][od], bb[bt][od + 2]);
                }
        }

        if (kt + 1 < NKCH) {
            const int nb = buf ^ 1;
            *(uint4*)&As[nb][grow][gc0 * 8]       = pa0;
            *(uint4*)&As[nb][grow][(gc0 + 1) * 8] = pa1;
            *(uint4*)&Bs[nb][grow][gc0 * 8]       = pb0;
            *(uint4*)&Bs[nb][grow][(gc0 + 1) * 8] = pb1;
            __syncthreads();
        }
    }

    #pragma unroll
    for (int mt = 0; mt < 4; ++mt) {
        const int row = by * 128 + wm * 64 + mt * 16 + (lane >> 2);
        #pragma unroll
        for (int nt = 0; nt < 4; ++nt) {
            const int col = bx * 128 + wn * 32 + nt * 8 + (lane & 3) * 2;
            const float b0 = bi[col], b1 = bi[col + 1];
            float* p0 = g_gi + (size_t)row * G3 + col;
            float* p1 = g_gi + (size_t)(row + 8) * G3 + col;
            *(float2*)p0 = make_float2(acc[mt][nt][0] + b0, acc[mt][nt][1] + b1);
            *(float2*)p1 = make_float2(acc[mt][nt][2] + b0, acc[mt][nt][3] + b1);
        }
    }
}

// ---------------- Phase 2: persistent recurrence via mma.sync bf16 hi/lo ----------------
// 128 CTAs = 4 batch-groups (16 rows) x 32 col-CTAs (16 h-cols = 48 gate-cols).
// h exchanged as packed bf16 hi/lo u32; h_old kept in registers per owner thread.
#define BSTR 520
#define REC_SMEM_BYTES (2 * 48 * BSTR * 2 + 2 * 16 * BSTR * 2 + 8 * 16 * 50 * 4)  // 158720

__global__ __launch_bounds__(256) void gru_rec_kernel(
    const float* __restrict__ h0, const float* __restrict__ Wh,
    const float* __restrict__ bhn, float* __restrict__ out)
{
    extern __shared__ char smem[];
    __nv_bfloat16* Bh = (__nv_bfloat16*)smem;            // [48][520]
    __nv_bfloat16* Bl = Bh + 48 * BSTR;                  // [48][520]
    __nv_bfloat16* Ah = Bl + 48 * BSTR;                  // [16][520]
    __nv_bfloat16* Al = Ah + 16 * BSTR;                  // [16][520]
    float*        parts = (float*)(Al + 16 * BSTR);      // [8][16][50]

    const int tid  = threadIdx.x;
    const int lane = tid & 31;
    const int ks   = tid >> 5;         // warp = k-split 0..7 (64 k per pass)
    const int bg   = blockIdx.x >> 5;  // batch group 0..3 (16 rows)
    const int ic   = blockIdx.x & 31;  // col group 0..31  (16 h-cols)

    // --- one-time: Wh slice -> bf16 hi/lo, B layout [j][k], j: 0-15 r, 16-31 z, 32-47 n
    for (int q = tid; q < 48 * 512; q += 256) {
        int k = q / 48;
        int j = q - k * 48;
        int gc = (j >> 4) * 512 + ic * 16 + (j & 15);
        float v = Wh[(size_t)k * G3 + gc];
        unsigned short hi = f2bf(v);
        unsigned short lo = f2bf(v - bf2f(hi));
        *reinterpret_cast<unsigned short*>(Bh + j * BSTR + k) = hi;
        *reinterpret_cast<unsigned short*>(Bl + j * BSTR + k) = lo;
    }

    // gate-thread output assignment: 256 outputs = 16 rows x 16 cols
    const int orow = tid >> 4;
    const int oc   = tid & 15;
    const int hcol = ic * 16 + oc;
    const int brow = bg * 16 + orow;
    const float bh = bhn[hcol];
    float hold = h0[brow * HDIM + hcol];   // owner-thread register copy of h_old

    const int lrow = lane & 15;
    const int lkof = (lane >> 4) * 8;
    const uint32_t* hp = g_hp + bg * 16 * HDIM;   // group's 16 rows, packed

    __syncthreads();

    for (int t = 0; t < T_STEPS; ++t) {
        // --- prefetch gi (DRAM latency hidden behind copy + GEMM) ---
        const float* gp = g_gi + ((size_t)t * BATCH + brow) * G3 + hcol;
        float gr = gp[0], gz = gp[512], gn = gp[1024];

        // --- unpack group's h (packed bf16 hi/lo) into A tiles: PRMT only, no cvt ---
        #pragma unroll
        for (int q = tid; q < 2048; q += 256) {     // 2048 uint4 covers 16x512 u32
            int m  = q >> 7;
            int kq = (q & 127) * 4;
            uint4 p = *(const uint4*)&hp[m * HDIM + kq];
            uint32_t hi01 = __byte_perm(p.x, p.y, 0x7632);
            uint32_t lo01 = __byte_perm(p.x, p.y, 0x5410);
            uint32_t hi23 = __byte_perm(p.z, p.w, 0x7632);
            uint32_t lo23 = __byte_perm(p.z, p.w, 0x5410);
            *(uint2*)(Ah + m * BSTR + kq) = make_uint2(hi01, hi23);
            *(uint2*)(Al + m * BSTR + kq) = make_uint2(lo01, lo23);
        }
        __syncthreads();

        // --- 3-pass GEMM: (Ah,Bh) + (Al,Bh) + (Ah,Bl), warp k-slice = 64 ---
        float acc[6][4];
        #pragma unroll
        for (int nt = 0; nt < 6; ++nt)
            #pragma unroll
            for (int i = 0; i < 4; ++i) acc[nt][i] = 0.f;

        #pragma unroll
        for (int p = 0; p < 3; ++p) {
            const __nv_bfloat16* Asrc = (p == 1) ? Al : Ah;
            const __nv_bfloat16* Bsrc = (p == 2) ? Bl : Bh;
            #pragma unroll
            for (int ki = 0; ki < 4; ++ki) {
                const int k0 = ks * 64 + ki * 16;
                uint32_t a[4];
                ldsm_x4(a[0], a[1], a[2], a[3],
                        s2u(Asrc + lrow * BSTR + k0 + lkof));
                uint32_t bb[3][4];
                #pragma unroll
                for (int bt = 0; bt < 3; ++bt)
                    ldsm_x4(bb[bt][0], bb[bt][1], bb[bt][2], bb[bt][3],
                            s2u(Bsrc + (bt * 16 + lrow) * BSTR + k0 + lkof));
                #pragma unroll
                for (int nt = 0; nt < 6; ++nt) {
                    const int bt = nt >> 1, od = nt & 1;
                    mma16816(acc[nt], a, bb[bt][od], bb[bt][od + 2]);
                }
            }
        }

        // --- stage k-split partials ---
        {
            const int pr  = lane >> 2;
            const int pcb = (lane & 3) * 2;
            #pragma unroll
            for (int nt = 0; nt < 6; ++nt) {
                const int col = nt * 8 + pcb;
                *(float2*)&parts[(ks * 16 + pr) * 50 + col]     = make_float2(acc[nt][0], acc[nt][1]);
                *(float2*)&parts[(ks * 16 + pr + 8) * 50 + col] = make_float2(acc[nt][2], acc[nt][3]);
            }
        }
        __syncthreads();

        // --- reduce 8 k-splits + gates + write ---
        {
            float sr = 0.f, sz = 0.f, sn = 0.f;
            #pragma unroll
            for (int k2 = 0; k2 < 8; ++k2) {
                const float* q = &parts[(k2 * 16 + orow) * 50];
                sr += q[oc]; sz += q[16 + oc]; sn += q[32 + oc];
            }
            float er = __expf(-(gr + sr));
            float rr = __fdividef(1.f, 1.f + er);
            float ez = __expf(-(gz + sz));
            float zz = __fdividef(1.f, 1.f + ez);
            float e2 = __expf(2.f * (gn + rr * (sn + bh)));
            float nn = 1.f - __fdividef(2.f, e2 + 1.f);   // tanh, saturates safely
            float hnew = (1.f - zz) * nn + zz * hold;
            hold = hnew;
            unsigned short hi = f2bf(hnew);
            unsigned short lo = f2bf(hnew - bf2f(hi));
            g_hp[brow * HDIM + hcol] = ((uint32_t)hi << 16) | lo;
            out[((size_t)t * BATCH + brow) * HDIM + hcol] = hnew;
        }

        // --- 32-CTA batch-group barrier ---
        __threadfence();
        __syncthreads();
        if (tid == 0) {
            atomicAdd(&g_bar[bg], 1);
            const int target = (t + 1) * 32;
            while (ld_acquire_gpu(&g_bar[bg]) < target) { }
        }
        __syncthreads();
    }
}

// ---------------- launch ----------------
extern "C" void kernel_launch(void* const* d_in, const int* in_sizes, int n_in,
                              void* d_out, int out_size)
{
    const float* x   = (const float*)d_in[0];   // [T,B,D]
    const float* h0  = (const float*)d_in[1];   // [B,H]
    const float* Wi  = (const float*)d_in[2];   // [D,3H]
    const float* Wh  = (const float*)d_in[3];   // [H,3H]
    const float* bi  = (const float*)d_in[4];   // [3H]
    const float* bhn = (const float*)d_in[5];   // [H]
    float* out = (float*)d_out;                 // [T,B,H]
    (void)in_sizes; (void)n_in; (void)out_size;

    cudaFuncSetAttribute(gru_rec_kernel,
                         cudaFuncAttributeMaxDynamicSharedMemorySize, REC_SMEM_BYTES);

    gru_init_kernel<<<32, 1024>>>(h0);

    conv_x_kernel<<<(MROWS * DDIM / 4) / 256, 256>>>(x);
    conv_w_kernel<<<dim3(16, 48), dim3(32, 8)>>>(Wi);

    dim3 g1(G3 / 128, MROWS / 128);   // (12, 256)
    gi_mma_kernel<<<g1, 256>>>(bi);

    gru_rec_kernel<<<128, 256, REC_SMEM_BYTES>>>(h0, Wh, bhn, out);
}